// round 13
// baseline (speedup 1.0000x reference)
#include <cuda_runtime.h>
#include <cstdint>

#define DEVINL __device__ __forceinline__

static constexpr int IN_F   = 256;
static constexpr int OUT_F  = 64;
static constexpr int M_TILE = 128;
static constexpr int NCHUNK = 64;      // K chunks: 4 inputs x 16 slots

// smem layout (bytes from 1024-aligned dynamic base)
static constexpr int SM_X    = 0;              // x panel: 16 cols x 130 pitch fp32 = 8320B
static constexpr int SM_B    = 8448;           // B frag stages: 3 x 8KB
static constexpr int SMEM_SZ = SM_B + 3 * 8192 + 1024;   // ~34KB -> 3 CTAs/SM

__device__ uint2 g_B[NCHUNK * 4 * 8 * 32];   // 512KB pre-packed f16 B fragments

DEVINL uint32_t smem_u32(const void* p) {
    uint32_t a;
    asm("{ .reg .u64 t; cvta.to.shared.u64 t, %1; cvt.u32.u64 %0, t; }" : "=r"(a) : "l"(p));
    return a;
}
DEVINL uint16_t f2h(float f) {
    uint16_t h; asm("cvt.rn.f16.f32 %0, %1;" : "=h"(h) : "f"(f)); return h;
}
DEVINL uint32_t packh2(float lo, float hi) {   // d = {lo, hi} as f16x2
    uint32_t r; asm("cvt.rn.f16x2.f32 %0, %1, %2;" : "=r"(r) : "f"(hi), "f"(lo)); return r;
}
DEVINL void sts32(uint32_t a, uint32_t v) {
    asm volatile("st.shared.b32 [%0], %1;" :: "r"(a), "r"(v) : "memory");
}
DEVINL float lds32f(uint32_t a) {
    float v; asm volatile("ld.shared.f32 %0, [%1];" : "=f"(v) : "r"(a)); return v;
}
DEVINL void lds64(uint32_t a, uint32_t& x, uint32_t& y) {
    asm volatile("ld.shared.v2.b32 {%0,%1}, [%2];" : "=r"(x), "=r"(y) : "r"(a));
}
DEVINL void cpasync16(uint32_t dst, const void* src) {
    asm volatile("cp.async.cg.shared.global [%0], [%1], 16;" :: "r"(dst), "l"(src) : "memory");
}
DEVINL void cp_commit() { asm volatile("cp.async.commit_group;" ::: "memory"); }
DEVINL void cp_wait1()  { asm volatile("cp.async.wait_group 1;" ::: "memory"); }
DEVINL void cp_wait0()  { asm volatile("cp.async.wait_group 0;" ::: "memory"); }
DEVINL void mma16(float* d, const uint32_t* A, uint32_t b0, uint32_t b1) {
    asm volatile(
        "mma.sync.aligned.m16n8k16.row.col.f32.f16.f16.f32 "
        "{%0,%1,%2,%3}, {%4,%5,%6,%7}, {%8,%9}, {%0,%1,%2,%3};"
        : "+f"(d[0]), "+f"(d[1]), "+f"(d[2]), "+f"(d[3])
        : "r"(A[0]), "r"(A[1]), "r"(A[2]), "r"(A[3]), "r"(b0), "r"(b1));
}

// symmetric uniform cubic B-spline bump: N(d), support (-1,3), peak at d=1
DEVINL float nbump(float d) {
    float a  = fabsf(d - 1.0f);
    float a2 = a * a;
    float c1 = fmaf(0.5f * a, a2, 0.66666667f - a2);   // 2/3 - a^2 + a^3/2
    float e  = 2.0f - a;
    float c2 = e * e * e * 0.16666667f;
    float r  = (a < 1.0f) ? c1 : c2;
    return (a < 2.0f) ? r : 0.0f;
}

// ---- pre-kernel: weights -> packed f16 B fragments ----
// entry e = ((c*4 + i)*8 + nb)*32 + lane
// b0 = {slot k0, k0+1}, b1 = {k0+8, k0+9}, k0 = 2*(lane&3), n = nb*8 + lane/4
__global__ void kan_expand(const float* __restrict__ bw, const float* __restrict__ sw) {
    int e = blockIdx.x * 256 + threadIdx.x;      // 0..65535
    int lane = e & 31, nb = (e >> 5) & 7, kq = (e >> 8) & 3, c = e >> 10;
    int n = nb * 8 + (lane >> 2);
    int k0 = 2 * (lane & 3);
    int i = c * 4 + kq;
    auto wv = [&](int s) -> float {
        if (s == 0) return bw[n * IN_F + i];
        if (s <= 13) return sw[(n * IN_F + i) * 13 + (s - 1)];
        return 0.0f;
    };
    uint32_t b0 = (uint32_t)f2h(wv(k0))     | ((uint32_t)f2h(wv(k0 + 1)) << 16);
    uint32_t b1 = (uint32_t)f2h(wv(k0 + 8)) | ((uint32_t)f2h(wv(k0 + 9)) << 16);
    g_B[e] = make_uint2(b0, b1);
}

// ---- main kernel: register-built A fragments, fp16 mma ----
__global__ void __launch_bounds__(256, 3)
kan_main(const float* __restrict__ x, float* __restrict__ out) {
    extern __shared__ char smem_raw[];
    const uint32_t sb = (smem_u32(smem_raw) + 1023u) & ~1023u;
    const int tid = threadIdx.x, wid = tid >> 5, lane = tid & 31;
    const int rowBase = blockIdx.x * M_TILE;

    const int   rloc = wid * 16 + (lane >> 2);        // fragment row in tile (and +8)
    const float k0f  = (float)(2 * (lane & 3));       // base slot
    const bool  kz   = ((lane & 3) == 0);             // lower half contains slot 0
    const bool  k6   = ((lane & 3) == 3);             // upper half = slots 14,15 -> 0

    float acc[8][4];
    #pragma unroll
    for (int nb = 0; nb < 8; ++nb)
        #pragma unroll
        for (int k = 0; k < 4; ++k) acc[nb][k] = 0.0f;

    // prologue: stage B(0) into ring slot 0
    {
        const char* src = (const char*)(g_B);
        #pragma unroll
        for (int u = 0; u < 2; ++u) {
            int v = tid + 256 * u;
            cpasync16(sb + SM_B + (uint32_t)v * 16u, src + (size_t)v * 16u);
        }
        cp_commit();
    }

    for (int c = 0; c < NCHUNK; ++c) {
        if ((c & 3) == 0) {   // refresh x panel (16 cols, transposed, pitch 130)
            __syncthreads();
            #pragma unroll
            for (int u2 = 0; u2 < 2; ++u2) {
                int v = tid + 256 * u2;          // 512 float4 slots
                int pr = v >> 2, q4 = v & 3;
                const float4 xv = *reinterpret_cast<const float4*>(
                    x + (size_t)(rowBase + pr) * IN_F + c * 4 + 4 * q4);
                uint32_t a0 = sb + SM_X + (uint32_t)((4 * q4) * 130 + pr) * 4u;
                sts32(a0,             __float_as_uint(xv.x));
                sts32(a0 + 130u * 4u, __float_as_uint(xv.y));
                sts32(a0 + 260u * 4u, __float_as_uint(xv.z));
                sts32(a0 + 390u * 4u, __float_as_uint(xv.w));
            }
        }

        if (c + 1 < NCHUNK) {      // prefetch B(c+1) into ring slot (c+1)%3
            const char* src = (const char*)(g_B) + (size_t)(c + 1) * 8192;
            const uint32_t dst = sb + SM_B + (uint32_t)((c + 1) % 3) * 8192u;
            #pragma unroll
            for (int u = 0; u < 2; ++u) {
                int v = tid + 256 * u;
                cpasync16(dst + (uint32_t)v * 16u, src + (size_t)v * 16u);
            }
            cp_commit();
            cp_wait1();
        } else {
            cp_wait0();
        }
        __syncthreads();

        const uint32_t bSt = sb + SM_B + (uint32_t)(c % 3) * 8192u;
        #pragma unroll
        for (int i = 0; i < 4; ++i) {
            // x for this (chunk, input) pair, rows rloc and rloc+8
            const uint32_t xa = sb + SM_X + (uint32_t)((((c & 3) * 4 + i) * 130)) * 4u;
            const float x0 = lds32f(xa + (uint32_t)rloc * 4u);
            const float x1 = lds32f(xa + (uint32_t)(rloc + 8) * 4u);

            float u0, u1, s0, s1;
            {
                const float xc0 = fminf(fmaxf(x0, -2.5f), 2.5f);
                const float xc1 = fminf(fmaxf(x1, -2.5f), 2.5f);
                u0 = (xc0 + 3.2f) * 2.5f;
                u1 = (xc1 + 3.2f) * 2.5f;
                s0 = __fdividef(x0, 1.0f + __expf(-x0));
                s1 = __fdividef(x1, 1.0f + __expf(-x1));
            }

            uint32_t A[4];
            {   // lower K-half: slots k0, k0+1  (slot 0 -> silu)
                const float d0 = u0 - k0f, d1 = u1 - k0f;
                float v00 = kz ? s0 : nbump(d0);
                float v10 = kz ? s1 : nbump(d1);
                A[0] = packh2(v00, nbump(d0 - 1.0f));
                A[1] = packh2(v10, nbump(d1 - 1.0f));
            }
            {   // upper K-half: slots k0+8, k0+9  (slots 14,15 -> 0)
                const float d0 = u0 - k0f - 8.0f, d1 = u1 - k0f - 8.0f;
                float a20 = k6 ? 0.0f : nbump(d0);
                float a21 = k6 ? 0.0f : nbump(d0 - 1.0f);
                float a30 = k6 ? 0.0f : nbump(d1);
                float a31 = k6 ? 0.0f : nbump(d1 - 1.0f);
                A[2] = packh2(a20, a21);
                A[3] = packh2(a30, a31);
            }

            #pragma unroll
            for (int nb = 0; nb < 8; ++nb) {
                uint32_t b0, b1;
                lds64(bSt + (uint32_t)(((i * 8 + nb) * 32 + lane)) * 8u, b0, b1);
                mma16(acc[nb], A, b0, b1);
            }
        }
        __syncthreads();
    }

    // ---- epilogue: direct C-fragment stores ----
    const int orow = wid * 16 + (lane >> 2);
    const int col  = 2 * (lane & 3);
    #pragma unroll
    for (int nb = 0; nb < 8; ++nb) {
        float2 v0; v0.x = acc[nb][0]; v0.y = acc[nb][1];
        float2 v1; v1.x = acc[nb][2]; v1.y = acc[nb][3];
        *reinterpret_cast<float2*>(out + (size_t)(rowBase + orow) * OUT_F + nb * 8 + col) = v0;
        *reinterpret_cast<float2*>(out + (size_t)(rowBase + orow + 8) * OUT_F + nb * 8 + col) = v1;
    }
}

extern "C" void kernel_launch(void* const* d_in, const int* in_sizes, int n_in,
                              void* d_out, int out_size) {
    const float* x  = (const float*)d_in[0];
    const float* bw = (const float*)d_in[1];
    const float* sw = (const float*)d_in[2];
    float* out = (float*)d_out;
    cudaFuncSetAttribute(kan_main, cudaFuncAttributeMaxDynamicSharedMemorySize, SMEM_SZ);
    kan_expand<<<256, 256>>>(bw, sw);
    kan_main<<<65536 / M_TILE, 256, SMEM_SZ>>>(x, out);
}

// round 15
// speedup vs baseline: 1.4829x; 1.4829x over previous
#include <cuda_runtime.h>
#include <cstdint>

#define DEVINL __device__ __forceinline__

static constexpr int IN_F   = 256;
static constexpr int OUT_F  = 64;
static constexpr int M_TILE = 128;
static constexpr int NCHUNK = 64;      // K chunks: 4 inputs x 16 slots

// smem layout (bytes from 1024-aligned dynamic base)
static constexpr int SM_X    = 0;                  // x panel: 16 cols x 130 pitch = 8320B
static constexpr int SM_A    = 8448;               // A tiles: 2 x 16KB (granule-permuted)
static constexpr int SM_B    = SM_A + 32768;       // B frags: 2 x 8KB
static constexpr int SMEM_SZ = SM_B + 16384 + 1024;  // 58624 -> 3 CTAs/SM

__device__ uint2 g_B[NCHUNK * 4 * 8 * 32];   // 512KB pre-packed f16 B fragments

DEVINL uint32_t smem_u32(const void* p) {
    uint32_t a;
    asm("{ .reg .u64 t; cvta.to.shared.u64 t, %1; cvt.u32.u64 %0, t; }" : "=r"(a) : "l"(p));
    return a;
}
DEVINL uint16_t f2h(float f) {
    uint16_t h; asm("cvt.rn.f16.f32 %0, %1;" : "=h"(h) : "f"(f)); return h;
}
DEVINL void sts128(uint32_t a, uint32_t x, uint32_t y, uint32_t z, uint32_t w) {
    asm volatile("st.shared.v4.b32 [%0], {%1,%2,%3,%4};" :: "r"(a), "r"(x), "r"(y), "r"(z), "r"(w) : "memory");
}
DEVINL void sts32(uint32_t a, uint32_t v) {
    asm volatile("st.shared.b32 [%0], %1;" :: "r"(a), "r"(v) : "memory");
}
DEVINL void sts16(uint32_t a, uint16_t v) {
    asm volatile("st.shared.u16 [%0], %1;" :: "r"(a), "h"(v) : "memory");
}
DEVINL float lds32f(uint32_t a) {
    float v; asm volatile("ld.shared.f32 %0, [%1];" : "=f"(v) : "r"(a)); return v;
}
DEVINL void lds64(uint32_t a, uint32_t& x, uint32_t& y) {
    asm volatile("ld.shared.v2.b32 {%0,%1}, [%2];" : "=r"(x), "=r"(y) : "r"(a));
}
DEVINL void ldsm4(uint32_t a, uint32_t& r0, uint32_t& r1, uint32_t& r2, uint32_t& r3) {
    asm volatile("ldmatrix.sync.aligned.m8n8.x4.shared.b16 {%0,%1,%2,%3}, [%4];"
                 : "=r"(r0), "=r"(r1), "=r"(r2), "=r"(r3) : "r"(a));
}
DEVINL void cpasync16(uint32_t dst, const void* src) {
    asm volatile("cp.async.cg.shared.global [%0], [%1], 16;" :: "r"(dst), "l"(src) : "memory");
}
DEVINL void cp_commit() { asm volatile("cp.async.commit_group;" ::: "memory"); }
DEVINL void cp_wait0()  { asm volatile("cp.async.wait_group 0;" ::: "memory"); }
DEVINL void mma16(float* d, const uint32_t* A, uint32_t b0, uint32_t b1) {
    asm volatile(
        "mma.sync.aligned.m16n8k16.row.col.f32.f16.f16.f32 "
        "{%0,%1,%2,%3}, {%4,%5,%6,%7}, {%8,%9}, {%0,%1,%2,%3};"
        : "+f"(d[0]), "+f"(d[1]), "+f"(d[2]), "+f"(d[3])
        : "r"(A[0]), "r"(A[1]), "r"(A[2]), "r"(A[3]), "r"(b0), "r"(b1));
}

// permuted A granule index: (i, row, half) -> 16B-granule index
DEVINL uint32_t a_g16(int i, int row, int h) {
    return (uint32_t)(i * 256 + 2 * row + (h ^ ((row >> 2) & 1)));
}

// ---- pre-kernel: weights -> packed f16 B fragments ----
// entry e = ((c*4 + i)*8 + nb)*32 + lane
// b0 = {slot k0, k0+1}, b1 = {k0+8, k0+9}, k0 = 2*(lane&3), n = nb*8 + lane/4
__global__ void kan_expand(const float* __restrict__ bw, const float* __restrict__ sw) {
    int e = blockIdx.x * 256 + threadIdx.x;      // 0..65535
    int lane = e & 31, nb = (e >> 5) & 7, kq = (e >> 8) & 3, c = e >> 10;
    int n = nb * 8 + (lane >> 2);
    int k0 = 2 * (lane & 3);
    int i = c * 4 + kq;
    auto wv = [&](int s) -> float {
        if (s == 0) return bw[n * IN_F + i];
        if (s <= 13) return sw[(n * IN_F + i) * 13 + (s - 1)];
        return 0.0f;
    };
    uint32_t b0 = (uint32_t)f2h(wv(k0))     | ((uint32_t)f2h(wv(k0 + 1)) << 16);
    uint32_t b1 = (uint32_t)f2h(wv(k0 + 8)) | ((uint32_t)f2h(wv(k0 + 9)) << 16);
    g_B[e] = make_uint2(b0, b1);
}

// produce one (row,i) feature row into permuted A tile at aBuf
DEVINL void produce_pair(uint32_t sb, uint32_t aBuf, int cc, int row, int i) {
    const float xv = lds32f(sb + SM_X + (uint32_t)((((cc & 3) * 4 + i) * 130) + row) * 4u);
    const float sl = __fdividef(xv, 1.0f + __expf(-xv));
    const float xc = fminf(fmaxf(xv, -2.5f), 2.5f);
    const float u  = (xc + 3.2f) * 2.5f;
    const float mf = floorf(u);
    const int   m  = (int)mf;                      // 1..14
    const float t = u - mf, t2 = t * t, t3 = t2 * t, omt = 1.0f - t;
    const float i6 = 1.0f / 6.0f;
    uint16_t hb[4];
    hb[0] = f2h(i6 * omt * omt * omt);
    hb[1] = f2h(i6 * (3.0f * t3 - 6.0f * t2 + 4.0f));
    hb[2] = f2h(i6 * (-3.0f * t3 + 3.0f * t2 + 3.0f * t + 1.0f));
    hb[3] = f2h(i6 * t3);

    const uint32_t g0 = aBuf + a_g16(i, row, 0) * 16u;
    const uint32_t g1 = aBuf + a_g16(i, row, 1) * 16u;
    sts128(g0, 0u, 0u, 0u, 0u);
    sts128(g1, 0u, 0u, 0u, 0u);
    sts16(g0, f2h(sl));                            // slot 0 = silu
    #pragma unroll
    for (int k = 0; k < 4; ++k) {
        const int s = m - 2 + k;                   // tap slot, -1..15
        if (s >= 1) {                              // s=0 is silu; s=14,15 harmless (w=0)
            const uint32_t base = (s & 8) ? g1 : g0;
            sts16(base + (uint32_t)(s & 7) * 2u, hb[k]);
        }
    }
}

// ---- main kernel ----
__global__ void __launch_bounds__(256, 3)
kan_main(const float* __restrict__ x, float* __restrict__ out) {
    extern __shared__ char smem_raw[];
    const uint32_t sb = (smem_u32(smem_raw) + 1023u) & ~1023u;
    const int tid = threadIdx.x, wid = tid >> 5, lane = tid & 31;
    const int rowBase = blockIdx.x * M_TILE;

    const int rg = wid & 3, cg = wid >> 2;         // 32-row group, 32-col group
    const int prow = tid & 127, pi0 = tid >> 7;    // producer role: i = pi0, pi0+2

    // ldsm lane addresses for the two 16-row blocks (granule idx * 16, i=0)
    uint32_t lA[2];
    {
        const int sub = lane >> 3;
        #pragma unroll
        for (int rb = 0; rb < 2; ++rb) {
            const int rrow = rg * 32 + rb * 16 + (sub & 1) * 8 + (lane & 7);
            lA[rb] = a_g16(0, rrow, sub >> 1) * 16u;
        }
    }

    float acc[2][4][4];
    #pragma unroll
    for (int rb = 0; rb < 2; ++rb)
        #pragma unroll
        for (int nb = 0; nb < 4; ++nb)
            #pragma unroll
            for (int k = 0; k < 4; ++k) acc[rb][nb][k] = 0.0f;

    // prologue: x panel(0), produce(0) -> Abuf0, cp B(0) -> slot0
    #pragma unroll
    for (int u2 = 0; u2 < 2; ++u2) {
        int v = tid + 256 * u2;
        int pr = v >> 2, q4 = v & 3;
        const float4 xv = *reinterpret_cast<const float4*>(
            x + (size_t)(rowBase + pr) * IN_F + 4 * q4);
        uint32_t a0 = sb + SM_X + (uint32_t)((4 * q4) * 130 + pr) * 4u;
        sts32(a0,             __float_as_uint(xv.x));
        sts32(a0 + 130u * 4u, __float_as_uint(xv.y));
        sts32(a0 + 260u * 4u, __float_as_uint(xv.z));
        sts32(a0 + 390u * 4u, __float_as_uint(xv.w));
    }
    __syncthreads();
    produce_pair(sb, sb + SM_A, 0, prow, pi0);
    produce_pair(sb, sb + SM_A, 0, prow, pi0 + 2);
    #pragma unroll
    for (int u = 0; u < 2; ++u) {
        int v = tid + 256 * u;
        cpasync16(sb + SM_B + (uint32_t)v * 16u, (const char*)g_B + (size_t)v * 16u);
    }
    cp_commit();

    for (int c = 0; c < NCHUNK; ++c) {
        cp_wait0();
        __syncthreads();     // A(c), B(c) ready; prior panel reads + mma(c-1) done

        if (c + 1 < NCHUNK) {
            const int cn = c + 1;
            if ((cn & 3) == 0) {   // refresh x panel for next group
                #pragma unroll
                for (int u2 = 0; u2 < 2; ++u2) {
                    int v = tid + 256 * u2;
                    int pr = v >> 2, q4 = v & 3;
                    const float4 xv = *reinterpret_cast<const float4*>(
                        x + (size_t)(rowBase + pr) * IN_F + cn * 4 + 4 * q4);
                    uint32_t a0 = sb + SM_X + (uint32_t)((4 * q4) * 130 + pr) * 4u;
                    sts32(a0,             __float_as_uint(xv.x));
                    sts32(a0 + 130u * 4u, __float_as_uint(xv.y));
                    sts32(a0 + 260u * 4u, __float_as_uint(xv.z));
                    sts32(a0 + 390u * 4u, __float_as_uint(xv.w));
                }
                __syncthreads();
            }
            // prefetch B(c+1) (overlaps produce + mma below)
            const char* src = (const char*)g_B + (size_t)cn * 8192;
            const uint32_t bdst = sb + SM_B + (uint32_t)(cn & 1) * 8192u;
            #pragma unroll
            for (int u = 0; u < 2; ++u) {
                int v = tid + 256 * u;
                cpasync16(bdst + (uint32_t)v * 16u, src + (size_t)v * 16u);
            }
            cp_commit();
            // produce A(c+1) into the other buffer
            const uint32_t aN = sb + SM_A + (uint32_t)(cn & 1) * 16384u;
            produce_pair(sb, aN, cn, prow, pi0);
            produce_pair(sb, aN, cn, prow, pi0 + 2);
        }

        // mma(c)
        const uint32_t aB = sb + SM_A + (uint32_t)(c & 1) * 16384u;
        const uint32_t bSt = sb + SM_B + (uint32_t)(c & 1) * 8192u;
        #pragma unroll
        for (int i = 0; i < 4; ++i) {
            uint32_t A0[4], A1[4];
            ldsm4(aB + lA[0] + (uint32_t)i * 4096u, A0[0], A0[1], A0[2], A0[3]);
            ldsm4(aB + lA[1] + (uint32_t)i * 4096u, A1[0], A1[1], A1[2], A1[3]);
            #pragma unroll
            for (int nb = 0; nb < 4; ++nb) {
                uint32_t b0, b1;
                lds64(bSt + (uint32_t)(((i * 8 + cg * 4 + nb) * 32 + lane)) * 8u, b0, b1);
                mma16(acc[0][nb], A0, b0, b1);
                mma16(acc[1][nb], A1, b0, b1);
            }
        }
    }

    // ---- epilogue: direct C-fragment stores ----
    #pragma unroll
    for (int rb = 0; rb < 2; ++rb) {
        const int orow = rg * 32 + rb * 16 + (lane >> 2);
        #pragma unroll
        for (int nb = 0; nb < 4; ++nb) {
            const int col = cg * 32 + nb * 8 + 2 * (lane & 3);
            float2 v0; v0.x = acc[rb][nb][0]; v0.y = acc[rb][nb][1];
            float2 v1; v1.x = acc[rb][nb][2]; v1.y = acc[rb][nb][3];
            *reinterpret_cast<float2*>(out + (size_t)(rowBase + orow) * OUT_F + col) = v0;
            *reinterpret_cast<float2*>(out + (size_t)(rowBase + orow + 8) * OUT_F + col) = v1;
        }
    }
}

extern "C" void kernel_launch(void* const* d_in, const int* in_sizes, int n_in,
                              void* d_out, int out_size) {
    const float* x  = (const float*)d_in[0];
    const float* bw = (const float*)d_in[1];
    const float* sw = (const float*)d_in[2];
    float* out = (float*)d_out;
    cudaFuncSetAttribute(kan_main, cudaFuncAttributeMaxDynamicSharedMemorySize, SMEM_SZ);
    kan_expand<<<256, 256>>>(bw, sw);
    kan_main<<<65536 / M_TILE, 256, SMEM_SZ>>>(x, out);
}

// round 16
// speedup vs baseline: 1.5177x; 1.0235x over previous
#include <cuda_runtime.h>
#include <cstdint>

#define DEVINL __device__ __forceinline__

static constexpr int IN_F   = 256;
static constexpr int OUT_F  = 64;
static constexpr int M_TILE = 128;
static constexpr int NCHUNK = 64;      // K chunks: 4 inputs x 16 slots

// smem layout (bytes from 1024-aligned dynamic base)
static constexpr int SM_X    = 0;                  // x panel: 16 cols x 130 pitch = 8320B
static constexpr int SM_A    = 8448;               // A tiles: 2 x 16KB (granule-permuted)
static constexpr int SM_B    = SM_A + 32768;       // B frags: 2 x 8KB
static constexpr int SMEM_SZ = SM_B + 16384 + 1024;  // 58624 -> 3 CTAs/SM

__device__ uint2 g_B[NCHUNK * 4 * 8 * 32];   // 512KB pre-packed f16 B fragments

DEVINL uint32_t smem_u32(const void* p) {
    uint32_t a;
    asm("{ .reg .u64 t; cvta.to.shared.u64 t, %1; cvt.u32.u64 %0, t; }" : "=r"(a) : "l"(p));
    return a;
}
DEVINL uint16_t f2h(float f) {
    uint16_t h; asm("cvt.rn.f16.f32 %0, %1;" : "=h"(h) : "f"(f)); return h;
}
DEVINL void sts128(uint32_t a, uint32_t x, uint32_t y, uint32_t z, uint32_t w) {
    asm volatile("st.shared.v4.b32 [%0], {%1,%2,%3,%4};" :: "r"(a), "r"(x), "r"(y), "r"(z), "r"(w) : "memory");
}
DEVINL void sts32(uint32_t a, uint32_t v) {
    asm volatile("st.shared.b32 [%0], %1;" :: "r"(a), "r"(v) : "memory");
}
DEVINL float lds32f(uint32_t a) {
    float v; asm volatile("ld.shared.f32 %0, [%1];" : "=f"(v) : "r"(a)); return v;
}
DEVINL void lds64(uint32_t a, uint32_t& x, uint32_t& y) {
    asm volatile("ld.shared.v2.b32 {%0,%1}, [%2];" : "=r"(x), "=r"(y) : "r"(a));
}
DEVINL void ldsm4(uint32_t a, uint32_t& r0, uint32_t& r1, uint32_t& r2, uint32_t& r3) {
    asm volatile("ldmatrix.sync.aligned.m8n8.x4.shared.b16 {%0,%1,%2,%3}, [%4];"
                 : "=r"(r0), "=r"(r1), "=r"(r2), "=r"(r3) : "r"(a));
}
DEVINL void cpasync16(uint32_t dst, const void* src) {
    asm volatile("cp.async.cg.shared.global [%0], [%1], 16;" :: "r"(dst), "l"(src) : "memory");
}
DEVINL void cp_commit() { asm volatile("cp.async.commit_group;" ::: "memory"); }
DEVINL void cp_wait0()  { asm volatile("cp.async.wait_group 0;" ::: "memory"); }
DEVINL void mma16(float* d, const uint32_t* A, uint32_t b0, uint32_t b1) {
    asm volatile(
        "mma.sync.aligned.m16n8k16.row.col.f32.f16.f16.f32 "
        "{%0,%1,%2,%3}, {%4,%5,%6,%7}, {%8,%9}, {%0,%1,%2,%3};"
        : "+f"(d[0]), "+f"(d[1]), "+f"(d[2]), "+f"(d[3])
        : "r"(A[0]), "r"(A[1]), "r"(A[2]), "r"(A[3]), "r"(b0), "r"(b1));
}

// permuted A granule index: (i, row, half) -> 16B-granule index
DEVINL uint32_t a_g16(int i, int row, int h) {
    return (uint32_t)(i * 256 + 2 * row + (h ^ ((row >> 2) & 1)));
}

// ---- pre-kernel: weights -> packed f16 B fragments ----
// entry e = ((c*4 + i)*8 + nb)*32 + lane
// b0 = {slot k0, k0+1}, b1 = {k0+8, k0+9}, k0 = 2*(lane&3), n = nb*8 + lane/4
__global__ void kan_expand(const float* __restrict__ bw, const float* __restrict__ sw) {
    int e = blockIdx.x * 256 + threadIdx.x;      // 0..65535
    int lane = e & 31, nb = (e >> 5) & 7, kq = (e >> 8) & 3, c = e >> 10;
    int n = nb * 8 + (lane >> 2);
    int k0 = 2 * (lane & 3);
    int i = c * 4 + kq;
    auto wv = [&](int s) -> float {
        if (s == 0) return bw[n * IN_F + i];
        if (s <= 13) return sw[(n * IN_F + i) * 13 + (s - 1)];
        return 0.0f;
    };
    uint32_t b0 = (uint32_t)f2h(wv(k0))     | ((uint32_t)f2h(wv(k0 + 1)) << 16);
    uint32_t b1 = (uint32_t)f2h(wv(k0 + 8)) | ((uint32_t)f2h(wv(k0 + 9)) << 16);
    g_B[e] = make_uint2(b0, b1);
}

// produce one (row,i) feature row: build 8 packed f16x2 words in registers,
// store with exactly 2 conflict-free STS128 (no zero-pass, no tap scatter).
DEVINL void produce_pair(uint32_t sb, uint32_t aBuf, int cc, int row, int i) {
    const float xv = lds32f(sb + SM_X + (uint32_t)((((cc & 3) * 4 + i) * 130) + row) * 4u);
    const float sl = __fdividef(xv, 1.0f + __expf(-xv));
    const float xc = fminf(fmaxf(xv, -2.5f), 2.5f);
    const float u  = (xc + 3.2f) * 2.5f;
    const float mf = floorf(u);
    const int   m  = (int)mf;                      // 1..14
    const float t = u - mf, t2 = t * t, t3 = t2 * t, omt = 1.0f - t;
    const float i6 = 1.0f / 6.0f;
    const uint32_t h0 = f2h(i6 * omt * omt * omt);
    const uint32_t h1 = f2h(i6 * (3.0f * t3 - 6.0f * t2 + 4.0f));
    const uint32_t h2 = f2h(i6 * (-3.0f * t3 + 3.0f * t2 + 3.0f * t + 1.0f));
    const uint32_t h3 = f2h(i6 * t3);
    const uint32_t hs = f2h(sl);

    // taps occupy slots m-2..m+1; words are slot pairs. q = m>>1, r = m&1.
    //  r==0: w[q-1] = {h0,h1}, w[q] = {h2,h3}
    //  r==1: w[q-1] = {0,h0},  w[q] = {h1,h2}, w[q+1] = {h3,0}
    const int q = m >> 1;
    const bool r = (m & 1) != 0;
    const uint32_t Wa = r ? (h0 << 16)        : (h0 | (h1 << 16));
    const uint32_t Wb = r ? (h1 | (h2 << 16)) : (h2 | (h3 << 16));
    const uint32_t Wc = r ? h3                : 0u;

    uint32_t w[8];
    #pragma unroll
    for (int j = 0; j < 8; ++j)
        w[j] = (j == q - 1) ? Wa : (j == q) ? Wb : (j == q + 1) ? Wc : 0u;
    w[0] = (w[0] & 0xFFFF0000u) | hs;              // slot 0 = silu (drops s<=0 taps)

    const uint32_t g0 = aBuf + a_g16(i, row, 0) * 16u;
    const uint32_t g1 = aBuf + a_g16(i, row, 1) * 16u;
    sts128(g0, w[0], w[1], w[2], w[3]);
    sts128(g1, w[4], w[5], w[6], w[7]);
}

// ---- main kernel ----
__global__ void __launch_bounds__(256, 3)
kan_main(const float* __restrict__ x, float* __restrict__ out) {
    extern __shared__ char smem_raw[];
    const uint32_t sb = (smem_u32(smem_raw) + 1023u) & ~1023u;
    const int tid = threadIdx.x, wid = tid >> 5, lane = tid & 31;
    const int rowBase = blockIdx.x * M_TILE;

    const int rg = wid & 3, cg = wid >> 2;         // 32-row group, 32-col group
    const int prow = tid & 127, pi0 = tid >> 7;    // producer role: i = pi0, pi0+2

    // ldsm lane addresses for the two 16-row blocks (granule idx * 16, i=0)
    uint32_t lA[2];
    {
        const int sub = lane >> 3;
        #pragma unroll
        for (int rb = 0; rb < 2; ++rb) {
            const int rrow = rg * 32 + rb * 16 + (sub & 1) * 8 + (lane & 7);
            lA[rb] = a_g16(0, rrow, sub >> 1) * 16u;
        }
    }

    float acc[2][4][4];
    #pragma unroll
    for (int rb = 0; rb < 2; ++rb)
        #pragma unroll
        for (int nb = 0; nb < 4; ++nb)
            #pragma unroll
            for (int k = 0; k < 4; ++k) acc[rb][nb][k] = 0.0f;

    // prologue: x panel(0), produce(0) -> Abuf0, cp B(0) -> slot0
    #pragma unroll
    for (int u2 = 0; u2 < 2; ++u2) {
        int v = tid + 256 * u2;
        int pr = v >> 2, q4 = v & 3;
        const float4 xv = *reinterpret_cast<const float4*>(
            x + (size_t)(rowBase + pr) * IN_F + 4 * q4);
        uint32_t a0 = sb + SM_X + (uint32_t)((4 * q4) * 130 + pr) * 4u;
        sts32(a0,             __float_as_uint(xv.x));
        sts32(a0 + 130u * 4u, __float_as_uint(xv.y));
        sts32(a0 + 260u * 4u, __float_as_uint(xv.z));
        sts32(a0 + 390u * 4u, __float_as_uint(xv.w));
    }
    __syncthreads();
    produce_pair(sb, sb + SM_A, 0, prow, pi0);
    produce_pair(sb, sb + SM_A, 0, prow, pi0 + 2);
    #pragma unroll
    for (int u = 0; u < 2; ++u) {
        int v = tid + 256 * u;
        cpasync16(sb + SM_B + (uint32_t)v * 16u, (const char*)g_B + (size_t)v * 16u);
    }
    cp_commit();

    for (int c = 0; c < NCHUNK; ++c) {
        cp_wait0();
        __syncthreads();     // A(c), B(c) ready; prior panel reads + mma(c-1) done

        if (c + 1 < NCHUNK) {
            const int cn = c + 1;
            if ((cn & 3) == 0) {   // refresh x panel for next group
                #pragma unroll
                for (int u2 = 0; u2 < 2; ++u2) {
                    int v = tid + 256 * u2;
                    int pr = v >> 2, q4 = v & 3;
                    const float4 xv = *reinterpret_cast<const float4*>(
                        x + (size_t)(rowBase + pr) * IN_F + cn * 4 + 4 * q4);
                    uint32_t a0 = sb + SM_X + (uint32_t)((4 * q4) * 130 + pr) * 4u;
                    sts32(a0,             __float_as_uint(xv.x));
                    sts32(a0 + 130u * 4u, __float_as_uint(xv.y));
                    sts32(a0 + 260u * 4u, __float_as_uint(xv.z));
                    sts32(a0 + 390u * 4u, __float_as_uint(xv.w));
                }
                __syncthreads();
            }
            // prefetch B(c+1) (overlaps produce + mma below)
            const char* src = (const char*)g_B + (size_t)cn * 8192;
            const uint32_t bdst = sb + SM_B + (uint32_t)(cn & 1) * 8192u;
            #pragma unroll
            for (int u = 0; u < 2; ++u) {
                int v = tid + 256 * u;
                cpasync16(bdst + (uint32_t)v * 16u, src + (size_t)v * 16u);
            }
            cp_commit();
            // produce A(c+1) into the other buffer
            const uint32_t aN = sb + SM_A + (uint32_t)(cn & 1) * 16384u;
            produce_pair(sb, aN, cn, prow, pi0);
            produce_pair(sb, aN, cn, prow, pi0 + 2);
        }

        // mma(c)
        const uint32_t aB = sb + SM_A + (uint32_t)(c & 1) * 16384u;
        const uint32_t bSt = sb + SM_B + (uint32_t)(c & 1) * 8192u;
        #pragma unroll
        for (int i = 0; i < 4; ++i) {
            uint32_t A0[4], A1[4];
            ldsm4(aB + lA[0] + (uint32_t)i * 4096u, A0[0], A0[1], A0[2], A0[3]);
            ldsm4(aB + lA[1] + (uint32_t)i * 4096u, A1[0], A1[1], A1[2], A1[3]);
            #pragma unroll
            for (int nb = 0; nb < 4; ++nb) {
                uint32_t b0, b1;
                lds64(bSt + (uint32_t)(((i * 8 + cg * 4 + nb) * 32 + lane)) * 8u, b0, b1);
                mma16(acc[0][nb], A0, b0, b1);
                mma16(acc[1][nb], A1, b0, b1);
            }
        }
    }

    // ---- epilogue: direct C-fragment stores ----
    #pragma unroll
    for (int rb = 0; rb < 2; ++rb) {
        const int orow = rg * 32 + rb * 16 + (lane >> 2);
        #pragma unroll
        for (int nb = 0; nb < 4; ++nb) {
            const int col = cg * 32 + nb * 8 + 2 * (lane & 3);
            float2 v0; v0.x = acc[rb][nb][0]; v0.y = acc[rb][nb][1];
            float2 v1; v1.x = acc[rb][nb][2]; v1.y = acc[rb][nb][3];
            *reinterpret_cast<float2*>(out + (size_t)(rowBase + orow) * OUT_F + col) = v0;
            *reinterpret_cast<float2*>(out + (size_t)(rowBase + orow + 8) * OUT_F + col) = v1;
        }
    }
}

extern "C" void kernel_launch(void* const* d_in, const int* in_sizes, int n_in,
                              void* d_out, int out_size) {
    const float* x  = (const float*)d_in[0];
    const float* bw = (const float*)d_in[1];
    const float* sw = (const float*)d_in[2];
    float* out = (float*)d_out;
    cudaFuncSetAttribute(kan_main, cudaFuncAttributeMaxDynamicSharedMemorySize, SMEM_SZ);
    kan_expand<<<256, 256>>>(bw, sw);
    kan_main<<<65536 / M_TILE, 256, SMEM_SZ>>>(x, out);
}

// round 17
// speedup vs baseline: 1.6938x; 1.1160x over previous
#include <cuda_runtime.h>
#include <cstdint>

#define DEVINL __device__ __forceinline__

static constexpr int IN_F   = 256;
static constexpr int OUT_F  = 64;
static constexpr int M_TILE = 256;
static constexpr int NCHUNK = 64;      // K chunks: 4 inputs x 16 slots

// smem layout (bytes from 1024-aligned dynamic base)
static constexpr int XPITCH  = 258;                // floats per col
static constexpr int SM_X    = 0;                  // x panel: 16 cols x 258 pitch = 16512B
static constexpr int SM_A    = 16512;              // A tiles: 2 x 32KB (granule-permuted)
static constexpr int SM_B    = SM_A + 65536;       // B frags: 2 x 8KB
static constexpr int SMEM_SZ = SM_B + 16384 + 1024;  // 99456 -> 2 CTAs/SM

__device__ uint2 g_B[NCHUNK * 4 * 8 * 32];   // 512KB pre-packed f16 B fragments

DEVINL uint32_t smem_u32(const void* p) {
    uint32_t a;
    asm("{ .reg .u64 t; cvta.to.shared.u64 t, %1; cvt.u32.u64 %0, t; }" : "=r"(a) : "l"(p));
    return a;
}
DEVINL uint16_t f2h(float f) {
    uint16_t h; asm("cvt.rn.f16.f32 %0, %1;" : "=h"(h) : "f"(f)); return h;
}
DEVINL void sts128(uint32_t a, uint32_t x, uint32_t y, uint32_t z, uint32_t w) {
    asm volatile("st.shared.v4.b32 [%0], {%1,%2,%3,%4};" :: "r"(a), "r"(x), "r"(y), "r"(z), "r"(w) : "memory");
}
DEVINL void sts32(uint32_t a, uint32_t v) {
    asm volatile("st.shared.b32 [%0], %1;" :: "r"(a), "r"(v) : "memory");
}
DEVINL float lds32f(uint32_t a) {
    float v; asm volatile("ld.shared.f32 %0, [%1];" : "=f"(v) : "r"(a)); return v;
}
DEVINL void lds64(uint32_t a, uint32_t& x, uint32_t& y) {
    asm volatile("ld.shared.v2.b32 {%0,%1}, [%2];" : "=r"(x), "=r"(y) : "r"(a));
}
DEVINL void ldsm4(uint32_t a, uint32_t& r0, uint32_t& r1, uint32_t& r2, uint32_t& r3) {
    asm volatile("ldmatrix.sync.aligned.m8n8.x4.shared.b16 {%0,%1,%2,%3}, [%4];"
                 : "=r"(r0), "=r"(r1), "=r"(r2), "=r"(r3) : "r"(a));
}
DEVINL void cpasync16(uint32_t dst, const void* src) {
    asm volatile("cp.async.cg.shared.global [%0], [%1], 16;" :: "r"(dst), "l"(src) : "memory");
}
DEVINL void cp_commit() { asm volatile("cp.async.commit_group;" ::: "memory"); }
DEVINL void cp_wait0()  { asm volatile("cp.async.wait_group 0;" ::: "memory"); }
DEVINL void mma16(float* d, const uint32_t* A, uint32_t b0, uint32_t b1) {
    asm volatile(
        "mma.sync.aligned.m16n8k16.row.col.f32.f16.f16.f32 "
        "{%0,%1,%2,%3}, {%4,%5,%6,%7}, {%8,%9}, {%0,%1,%2,%3};"
        : "+f"(d[0]), "+f"(d[1]), "+f"(d[2]), "+f"(d[3])
        : "r"(A[0]), "r"(A[1]), "r"(A[2]), "r"(A[3]), "r"(b0), "r"(b1));
}

// permuted A granule index: (i, row(0..255), half) -> 16B-granule index
DEVINL uint32_t a_g16(int i, int row, int h) {
    return (uint32_t)(i * 512 + 2 * row + (h ^ ((row >> 2) & 1)));
}

// ---- pre-kernel: weights -> packed f16 B fragments ----
// entry e = ((c*4 + i)*8 + nb)*32 + lane
// b0 = {slot k0, k0+1}, b1 = {k0+8, k0+9}, k0 = 2*(lane&3), n = nb*8 + lane/4
__global__ void kan_expand(const float* __restrict__ bw, const float* __restrict__ sw) {
    int e = blockIdx.x * 256 + threadIdx.x;      // 0..65535
    int lane = e & 31, nb = (e >> 5) & 7, kq = (e >> 8) & 3, c = e >> 10;
    int n = nb * 8 + (lane >> 2);
    int k0 = 2 * (lane & 3);
    int i = c * 4 + kq;
    auto wv = [&](int s) -> float {
        if (s == 0) return bw[n * IN_F + i];
        if (s <= 13) return sw[(n * IN_F + i) * 13 + (s - 1)];
        return 0.0f;
    };
    uint32_t b0 = (uint32_t)f2h(wv(k0))     | ((uint32_t)f2h(wv(k0 + 1)) << 16);
    uint32_t b1 = (uint32_t)f2h(wv(k0 + 8)) | ((uint32_t)f2h(wv(k0 + 9)) << 16);
    g_B[e] = make_uint2(b0, b1);
}

// produce one (row,i) feature row: 8 packed f16x2 words, 2 conflict-free STS128
DEVINL void produce_pair(uint32_t sb, uint32_t aBuf, int cc, int row, int i) {
    const float xv = lds32f(sb + SM_X + (uint32_t)((((cc & 3) * 4 + i) * XPITCH) + row) * 4u);
    const float sl = __fdividef(xv, 1.0f + __expf(-xv));
    const float xc = fminf(fmaxf(xv, -2.5f), 2.5f);
    const float u  = (xc + 3.2f) * 2.5f;
    const float mf = floorf(u);
    const int   m  = (int)mf;                      // 1..14
    const float t = u - mf, t2 = t * t, t3 = t2 * t, omt = 1.0f - t;
    const float i6 = 1.0f / 6.0f;
    const uint32_t h0 = f2h(i6 * omt * omt * omt);
    const uint32_t h1 = f2h(i6 * (3.0f * t3 - 6.0f * t2 + 4.0f));
    const uint32_t h2 = f2h(i6 * (-3.0f * t3 + 3.0f * t2 + 3.0f * t + 1.0f));
    const uint32_t h3 = f2h(i6 * t3);
    const uint32_t hs = f2h(sl);

    const int q = m >> 1;
    const bool r = (m & 1) != 0;
    const uint32_t Wa = r ? (h0 << 16)        : (h0 | (h1 << 16));
    const uint32_t Wb = r ? (h1 | (h2 << 16)) : (h2 | (h3 << 16));
    const uint32_t Wc = r ? h3                : 0u;

    uint32_t w[8];
    #pragma unroll
    for (int j = 0; j < 8; ++j)
        w[j] = (j == q - 1) ? Wa : (j == q) ? Wb : (j == q + 1) ? Wc : 0u;
    w[0] = (w[0] & 0xFFFF0000u) | hs;              // slot 0 = silu (drops s<=0 taps)

    sts128(aBuf + a_g16(i, row, 0) * 16u, w[0], w[1], w[2], w[3]);
    sts128(aBuf + a_g16(i, row, 1) * 16u, w[4], w[5], w[6], w[7]);
}

DEVINL void stage_x(uint32_t sb, const float* __restrict__ x, int rowBase, int cc, int tid) {
    #pragma unroll
    for (int u2 = 0; u2 < 4; ++u2) {
        int v = tid + 256 * u2;               // 1024 float4 slots
        int pr = v >> 2, q4 = v & 3;
        const float4 xv = *reinterpret_cast<const float4*>(
            x + (size_t)(rowBase + pr) * IN_F + cc * 4 + 4 * q4);
        uint32_t a0 = sb + SM_X + (uint32_t)((4 * q4) * XPITCH + pr) * 4u;
        sts32(a0,                  __float_as_uint(xv.x));
        sts32(a0 + XPITCH * 4u,    __float_as_uint(xv.y));
        sts32(a0 + XPITCH * 8u,    __float_as_uint(xv.z));
        sts32(a0 + XPITCH * 12u,   __float_as_uint(xv.w));
    }
}

// ---- main kernel ----
__global__ void __launch_bounds__(256, 2)
kan_main(const float* __restrict__ x, float* __restrict__ out) {
    extern __shared__ char smem_raw[];
    const uint32_t sb = (smem_u32(smem_raw) + 1023u) & ~1023u;
    const int tid = threadIdx.x, wid = tid >> 5, lane = tid & 31;
    const int rowBase = blockIdx.x * M_TILE;

    // producer role: thread owns row tid, all 4 i
    // consumer role: warp owns rows wid*32..+31, all 64 cols

    // ldsm lane addresses for the two 16-row blocks (granule idx * 16, i=0)
    uint32_t lA[2];
    {
        const int sub = lane >> 3;
        #pragma unroll
        for (int rb = 0; rb < 2; ++rb) {
            const int rrow = wid * 32 + rb * 16 + (sub & 1) * 8 + (lane & 7);
            lA[rb] = a_g16(0, rrow, sub >> 1) * 16u;
        }
    }

    float acc[2][8][4];
    #pragma unroll
    for (int rb = 0; rb < 2; ++rb)
        #pragma unroll
        for (int nb = 0; nb < 8; ++nb)
            #pragma unroll
            for (int k = 0; k < 4; ++k) acc[rb][nb][k] = 0.0f;

    // prologue: x panel(0), produce(0) -> Abuf0, cp B(0) -> slot0
    stage_x(sb, x, rowBase, 0, tid);
    __syncthreads();
    #pragma unroll
    for (int i = 0; i < 4; ++i) produce_pair(sb, sb + SM_A, 0, tid, i);
    #pragma unroll
    for (int u = 0; u < 2; ++u) {
        int v = tid + 256 * u;
        cpasync16(sb + SM_B + (uint32_t)v * 16u, (const char*)g_B + (size_t)v * 16u);
    }
    cp_commit();

    for (int c = 0; c < NCHUNK; ++c) {
        cp_wait0();
        __syncthreads();     // A(c), B(c) ready; prior panel reads + mma(c-1) done

        if (c + 1 < NCHUNK) {
            const int cn = c + 1;
            if ((cn & 3) == 0) {   // refresh x panel for next group
                stage_x(sb, x, rowBase, cn, tid);
                __syncthreads();
            }
            // prefetch B(c+1) (overlaps produce + mma below)
            const char* src = (const char*)g_B + (size_t)cn * 8192;
            const uint32_t bdst = sb + SM_B + (uint32_t)(cn & 1) * 8192u;
            #pragma unroll
            for (int u = 0; u < 2; ++u) {
                int v = tid + 256 * u;
                cpasync16(bdst + (uint32_t)v * 16u, src + (size_t)v * 16u);
            }
            cp_commit();
            // produce A(c+1) into the other buffer
            const uint32_t aN = sb + SM_A + (uint32_t)(cn & 1) * 32768u;
            #pragma unroll
            for (int i = 0; i < 4; ++i) produce_pair(sb, aN, cn, tid, i);
        }

        // mma(c): warp covers 32 rows x 64 cols
        const uint32_t aB = sb + SM_A + (uint32_t)(c & 1) * 32768u;
        const uint32_t bSt = sb + SM_B + (uint32_t)(c & 1) * 8192u;
        #pragma unroll
        for (int i = 0; i < 4; ++i) {
            uint32_t A0[4], A1[4];
            ldsm4(aB + lA[0] + (uint32_t)i * 8192u, A0[0], A0[1], A0[2], A0[3]);
            ldsm4(aB + lA[1] + (uint32_t)i * 8192u, A1[0], A1[1], A1[2], A1[3]);
            #pragma unroll
            for (int nb = 0; nb < 8; ++nb) {
                uint32_t b0, b1;
                lds64(bSt + (uint32_t)(((i * 8 + nb) * 32 + lane)) * 8u, b0, b1);
                mma16(acc[0][nb], A0, b0, b1);
                mma16(acc[1][nb], A1, b0, b1);
            }
        }
    }

    // ---- epilogue: direct C-fragment stores ----
    #pragma unroll
    for (int rb = 0; rb < 2; ++rb) {
        const int orow = wid * 32 + rb * 16 + (lane >> 2);
        #pragma unroll
        for (int nb = 0; nb < 8; ++nb) {
            const int col = nb * 8 + 2 * (lane & 3);
            float2 v0; v0.x = acc[rb][nb][0]; v0.y = acc[rb][nb][1];
            float2 v1; v1.x = acc[rb][nb][2]; v1.y = acc[rb][nb][3];
            *reinterpret_cast<float2*>(out + (size_t)(rowBase + orow) * OUT_F + col) = v0;
            *reinterpret_cast<float2*>(out + (size_t)(rowBase + orow + 8) * OUT_F + col) = v1;
        }
    }
}

extern "C" void kernel_launch(void* const* d_in, const int* in_sizes, int n_in,
                              void* d_out, int out_size) {
    const float* x  = (const float*)d_in[0];
    const float* bw = (const float*)d_in[1];
    const float* sw = (const float*)d_in[2];
    float* out = (float*)d_out;
    cudaFuncSetAttribute(kan_main, cudaFuncAttributeMaxDynamicSharedMemorySize, SMEM_SZ);
    kan_expand<<<256, 256>>>(bw, sw);
    kan_main<<<65536 / M_TILE, 256, SMEM_SZ>>>(x, out);
}